// round 6
// baseline (speedup 1.0000x reference)
#include <cuda_runtime.h>
#include <cuda_bf16.h>
#include <math.h>
#include <stdint.h>

// ---------------- problem constants ----------------
#define ND 100000
#define NP 100000
#define EE 800000
#define HID 128
#define LDA 136  // padded bf16 row stride in smem (128 + 8)

// ---------------- scratch (device globals) ----------------
__device__ float g_h_d[ND * HID];
__device__ float g_h_p[NP * HID];
__device__ float g_fs_d[ND * HID];
__device__ float g_fs_p[NP * HID];
__device__ float g_agg_d[ND * HID];
__device__ float g_agg_p[NP * HID];
__device__ float g_el_d[ND * 4];
__device__ float g_er_p[NP * 4];
__device__ float g_el_p[NP * 4];
__device__ float g_er_d[ND * 4];
__device__ float g_Ut_dp[4 * HID];
__device__ float g_Ut_pd[4 * HID];
__device__ int g_deg_p[NP];
__device__ int g_deg_d[ND];
__device__ int g_indptr_p[NP + 1];
__device__ int g_indptr_d[ND + 1];
__device__ int g_cursor_p[NP + 1];
__device__ int g_cursor_d[ND + 1];
__device__ int g_csrc_p[EE];
__device__ int g_csrc_d[EE];
__device__ int g_part_p[1024];
__device__ int g_part_d[1024];
// 6 weight matrices x {hi,lo}: transposed bf16 [n][k], 32KB each
__device__ __align__(16) __nv_bfloat16 g_wimg[6][2][128 * 128];

__device__ __forceinline__ float lrelu(float v) { return v > 0.f ? v : 0.2f * v; }

__device__ __forceinline__ uint32_t smem_u32(const void* p) {
    uint32_t a;
    asm("{ .reg .u64 t; cvta.to.shared.u64 t, %1; cvt.u32.u64 %0, t; }" : "=r"(a) : "l"(p));
    return a;
}

// ---------------- prep: W [128k x 128n] fp32 -> transposed bf16 hi/lo [n][k] ----------------
__global__ void prep_w_kernel(const float* __restrict__ W,
                              __nv_bfloat16* __restrict__ hi,
                              __nv_bfloat16* __restrict__ lo)
{
    int idx = blockIdx.x * 256 + threadIdx.x;  // 0..16383
    int n = idx >> 7, k = idx & 127;
    float v = W[k * 128 + n];
    __nv_bfloat16 h = __float2bfloat16(v);
    float r = v - __bfloat162float(h);
    hi[n * 128 + k] = h;
    lo[n * 128 + k] = __float2bfloat16(r);
}

// ---------------- mma.sync bf16 split-3 GEMM with ldmatrix ----------------
__device__ __forceinline__ void mma_bf16(float* d, const uint32_t* a, uint32_t b0, uint32_t b1)
{
    asm volatile(
        "mma.sync.aligned.m16n8k16.row.col.f32.bf16.bf16.f32 "
        "{%0,%1,%2,%3}, {%4,%5,%6,%7}, {%8,%9}, {%0,%1,%2,%3};"
        : "+f"(d[0]), "+f"(d[1]), "+f"(d[2]), "+f"(d[3])
        : "r"(a[0]), "r"(a[1]), "r"(a[2]), "r"(a[3]), "r"(b0), "r"(b1));
}

__device__ __forceinline__ void ldm4(uint32_t* r, uint32_t addr)
{
    asm volatile("ldmatrix.sync.aligned.m8n8.x4.shared.b16 {%0,%1,%2,%3}, [%4];"
                 : "=r"(r[0]), "=r"(r[1]), "=r"(r[2]), "=r"(r[3]) : "r"(addr));
}

#define SM_TOTAL (4 * 128 * LDA * 2)  // 139264 B

template <bool RELU, bool HAS_BIAS>
__global__ void __launch_bounds__(256) gemm_mma(
    const float* __restrict__ A,
    const __nv_bfloat16* __restrict__ wHi, const __nv_bfloat16* __restrict__ wLo,
    const float* __restrict__ bias, float* __restrict__ out, int M)
{
    extern __shared__ __nv_bfloat16 sm[];
    __nv_bfloat16* sAh = sm;
    __nv_bfloat16* sAl = sm + 128 * LDA;
    __nv_bfloat16* sWh = sm + 2 * 128 * LDA;
    __nv_bfloat16* sWl = sm + 3 * 128 * LDA;
    const int tid = threadIdx.x;
    const int row0 = blockIdx.x * 128;

    // load W images [n][k] -> padded smem, vectorized 16B
    {
        const uint4* wh = reinterpret_cast<const uint4*>(wHi);
        const uint4* wl = reinterpret_cast<const uint4*>(wLo);
        for (int i = tid; i < 2048; i += 256) {
            int n = i >> 4, kc = i & 15;  // kc indexes 8-bf16 chunks
            *reinterpret_cast<uint4*>(&sWh[n * LDA + kc * 8]) = wh[i];
            *reinterpret_cast<uint4*>(&sWl[n * LDA + kc * 8]) = wl[i];
        }
    }
    // load + split-convert A tile
    {
        const float4* A4 = reinterpret_cast<const float4*>(A);
        for (int i = tid; i < 4096; i += 256) {
            int r = i >> 5, c4 = (i & 31) << 2;
            float4 a = make_float4(0.f, 0.f, 0.f, 0.f);
            if (row0 + r < M) a = A4[(size_t)(row0 + r) * 32 + (i & 31)];
            __nv_bfloat16 h0 = __float2bfloat16(a.x), h1 = __float2bfloat16(a.y);
            __nv_bfloat16 h2 = __float2bfloat16(a.z), h3 = __float2bfloat16(a.w);
            *reinterpret_cast<__nv_bfloat162*>(&sAh[r * LDA + c4])     = __halves2bfloat162(h0, h1);
            *reinterpret_cast<__nv_bfloat162*>(&sAh[r * LDA + c4 + 2]) = __halves2bfloat162(h2, h3);
            *reinterpret_cast<__nv_bfloat162*>(&sAl[r * LDA + c4]) = __halves2bfloat162(
                __float2bfloat16(a.x - __bfloat162float(h0)),
                __float2bfloat16(a.y - __bfloat162float(h1)));
            *reinterpret_cast<__nv_bfloat162*>(&sAl[r * LDA + c4 + 2]) = __halves2bfloat162(
                __float2bfloat16(a.z - __bfloat162float(h2)),
                __float2bfloat16(a.w - __bfloat162float(h3)));
        }
    }
    __syncthreads();

    const int wid = tid >> 5, lane = tid & 31;
    const int wm = wid >> 1, wn = wid & 1;       // 4x2 warp grid
    const int rbase = wm * 32, cbase = wn * 64;  // warp tile 32x64
    const int qr = lane >> 2, qc = (lane & 3) * 2;
    const int lr = lane & 15, lcb = (lane >> 4) * 16;  // ldmatrix row, col-bytes

    // per-lane ldmatrix base addresses (bytes), ks adds 32B each step
    uint32_t aH[2], aL[2], bHa[4], bLa[4];
    {
        uint32_t sbAh = smem_u32(sAh), sbAl = smem_u32(sAl);
        uint32_t sbWh = smem_u32(sWh), sbWl = smem_u32(sWl);
#pragma unroll
        for (int t = 0; t < 2; t++) {
            uint32_t off = (uint32_t)(rbase + t * 16 + lr) * (LDA * 2) + lcb;
            aH[t] = sbAh + off; aL[t] = sbAl + off;
        }
#pragma unroll
        for (int jp = 0; jp < 4; jp++) {
            uint32_t off = (uint32_t)(cbase + jp * 16 + lr) * (LDA * 2) + lcb;
            bHa[jp] = sbWh + off; bLa[jp] = sbWl + off;
        }
    }

    float d[2][8][4];
#pragma unroll
    for (int t = 0; t < 2; t++)
#pragma unroll
        for (int j = 0; j < 8; j++) {
            d[t][j][0] = 0.f; d[t][j][1] = 0.f; d[t][j][2] = 0.f; d[t][j][3] = 0.f;
        }

#pragma unroll 2
    for (int ks = 0; ks < 8; ks++) {
        const uint32_t ko = ks * 32;
        uint32_t ah[2][4], al[2][4];
        ldm4(ah[0], aH[0] + ko); ldm4(ah[1], aH[1] + ko);
        ldm4(al[0], aL[0] + ko); ldm4(al[1], aL[1] + ko);
#pragma unroll
        for (int jp = 0; jp < 4; jp++) {
            // regs: r0=b0(j_even), r1=b0(j_odd), r2=b1(j_even), r3=b1(j_odd)
            uint32_t bh[4], bl[4];
            ldm4(bh, bHa[jp] + ko);
            ldm4(bl, bLa[jp] + ko);
            const int je = jp * 2, jo = jp * 2 + 1;
#pragma unroll
            for (int t = 0; t < 2; t++) {
                mma_bf16(d[t][je], ah[t], bh[0], bh[2]);
                mma_bf16(d[t][je], al[t], bh[0], bh[2]);
                mma_bf16(d[t][je], ah[t], bl[0], bl[2]);
                mma_bf16(d[t][jo], ah[t], bh[1], bh[3]);
                mma_bf16(d[t][jo], al[t], bh[1], bh[3]);
                mma_bf16(d[t][jo], ah[t], bl[1], bl[3]);
            }
        }
    }

    // epilogue: D frag (t,j): rows rbase+t*16+qr (+8), cols cbase+j*8+qc (+1)
#pragma unroll
    for (int t = 0; t < 2; t++) {
        int r0 = row0 + rbase + t * 16 + qr;
#pragma unroll
        for (int j = 0; j < 8; j++) {
            int c0 = cbase + j * 8 + qc;
            float2 bv = make_float2(0.f, 0.f);
            if (HAS_BIAS) bv = __ldg(reinterpret_cast<const float2*>(bias + c0));
            float2 o0 = make_float2(d[t][j][0] + bv.x, d[t][j][1] + bv.y);
            float2 o1 = make_float2(d[t][j][2] + bv.x, d[t][j][3] + bv.y);
            if (RELU) {
                o0.x = fmaxf(o0.x, 0.f); o0.y = fmaxf(o0.y, 0.f);
                o1.x = fmaxf(o1.x, 0.f); o1.y = fmaxf(o1.y, 0.f);
            }
            if (r0 < M)
                *reinterpret_cast<float2*>(&out[(size_t)r0 * 128 + c0]) = o0;
            if (r0 + 8 < M)
                *reinterpret_cast<float2*>(&out[(size_t)(r0 + 8) * 128 + c0]) = o1;
        }
    }
}

// ---------------- misc small kernels ----------------
__global__ void zero_kernel(int* __restrict__ a, int n)
{
    int i = blockIdx.x * blockDim.x + threadIdx.x;
    if (i < n) a[i] = 0;
}

__global__ void fold_attn_kernel(const float* __restrict__ W,
                                 const float* __restrict__ ar,
                                 float* __restrict__ Ut)
{
    int k = threadIdx.x;
#pragma unroll
    for (int h = 0; h < 4; h++) {
        float s = 0.f;
#pragma unroll
        for (int d = 0; d < 32; d++)
            s += W[k * 128 + h * 32 + d] * ar[h * 32 + d];
        Ut[h * 128 + k] = s;
    }
}

__global__ void __launch_bounds__(256) er_kernel(
    const float* __restrict__ hfeat, const float* __restrict__ Ut,
    float* __restrict__ er, int n)
{
    int gw = (blockIdx.x * blockDim.x + threadIdx.x) >> 5;
    if (gw >= n) return;
    const int lane = threadIdx.x & 31;
    float4 f = reinterpret_cast<const float4*>(hfeat)[(size_t)gw * 32 + lane];
    const float4* Ut4 = reinterpret_cast<const float4*>(Ut);
    float p[4];
#pragma unroll
    for (int h = 0; h < 4; h++) {
        float4 u = __ldg(Ut4 + h * 32 + lane);
        p[h] = f.x * u.x + f.y * u.y + f.z * u.z + f.w * u.w;
    }
#pragma unroll
    for (int o = 16; o > 0; o >>= 1) {
#pragma unroll
        for (int h = 0; h < 4; h++)
            p[h] += __shfl_xor_sync(0xffffffffu, p[h], o);
    }
    if (lane == 0)
        reinterpret_cast<float4*>(er)[gw] = make_float4(p[0], p[1], p[2], p[3]);
}

__global__ void __launch_bounds__(256) el_kernel(
    const float* __restrict__ fs, const float* __restrict__ al,
    float* __restrict__ el, int n)
{
    int gw = (blockIdx.x * blockDim.x + threadIdx.x) >> 5;
    if (gw >= n) return;
    const int lane = threadIdx.x & 31;
    const int h = lane >> 3;
    float4 f = reinterpret_cast<const float4*>(fs)[(size_t)gw * 32 + lane];
    float4 a = __ldg(reinterpret_cast<const float4*>(al) + lane);
    float p = f.x * a.x + f.y * a.y + f.z * a.z + f.w * a.w;
    p += __shfl_xor_sync(0xffffffffu, p, 1);
    p += __shfl_xor_sync(0xffffffffu, p, 2);
    p += __shfl_xor_sync(0xffffffffu, p, 4);
    if ((lane & 7) == 0) el[(size_t)gw * 4 + h] = p;
}

// ---------------- CSR build ----------------
__global__ void count_kernel(const int* __restrict__ dst, int* __restrict__ deg, int E)
{
    int i = blockIdx.x * blockDim.x + threadIdx.x;
    if (i < E) atomicAdd(&deg[dst[i]], 1);
}

__global__ void __launch_bounds__(1024) scan_partA(const int* __restrict__ deg,
                                                   int* __restrict__ part, int n)
{
    __shared__ int ws[32];
    const int tid = threadIdx.x, lane = tid & 31, wid = tid >> 5;
    int i = blockIdx.x * 1024 + tid;
    int v = (i < n) ? deg[i] : 0;
    int s = v;
#pragma unroll
    for (int o = 16; o > 0; o >>= 1) s += __shfl_xor_sync(0xffffffffu, s, o);
    if (lane == 0) ws[wid] = s;
    __syncthreads();
    if (wid == 0) {
        int t = ws[lane];
#pragma unroll
        for (int o = 16; o > 0; o >>= 1) t += __shfl_xor_sync(0xffffffffu, t, o);
        if (lane == 0) part[blockIdx.x] = t;
    }
}

__global__ void __launch_bounds__(1024) scan_partB(int* __restrict__ part,
                                                   int* __restrict__ indptr,
                                                   int nb, int n)
{
    __shared__ int ws[32];
    const int tid = threadIdx.x, lane = tid & 31, wid = tid >> 5;
    int v = (tid < nb) ? part[tid] : 0;
    int x = v;
#pragma unroll
    for (int o = 1; o < 32; o <<= 1) {
        int y = __shfl_up_sync(0xffffffffu, x, o);
        if (lane >= o) x += y;
    }
    if (lane == 31) ws[wid] = x;
    __syncthreads();
    if (wid == 0) {
        int s = ws[lane];
#pragma unroll
        for (int o = 1; o < 32; o <<= 1) {
            int y = __shfl_up_sync(0xffffffffu, s, o);
            if (lane >= o) s += y;
        }
        ws[lane] = s;
    }
    __syncthreads();
    int excl = x - v + (wid ? ws[wid - 1] : 0);
    if (tid < nb) part[tid] = excl;
    __syncthreads();
    if (tid == 0) indptr[n] = ws[31];
}

__global__ void __launch_bounds__(1024) scan_partC(const int* __restrict__ deg,
                                                   const int* __restrict__ part,
                                                   int* __restrict__ indptr,
                                                   int* __restrict__ cursor, int n)
{
    __shared__ int ws[32];
    const int tid = threadIdx.x, lane = tid & 31, wid = tid >> 5;
    int i = blockIdx.x * 1024 + tid;
    int v = (i < n) ? deg[i] : 0;
    int x = v;
#pragma unroll
    for (int o = 1; o < 32; o <<= 1) {
        int y = __shfl_up_sync(0xffffffffu, x, o);
        if (lane >= o) x += y;
    }
    if (lane == 31) ws[wid] = x;
    __syncthreads();
    if (wid == 0) {
        int s = ws[lane];
#pragma unroll
        for (int o = 1; o < 32; o <<= 1) {
            int y = __shfl_up_sync(0xffffffffu, s, o);
            if (lane >= o) s += y;
        }
        ws[lane] = s;
    }
    __syncthreads();
    int excl = part[blockIdx.x] + x - v + (wid ? ws[wid - 1] : 0);
    if (i < n) { indptr[i] = excl; cursor[i] = excl; }
}

__global__ void scatter_kernel(const int* __restrict__ src, const int* __restrict__ dst,
                               int* __restrict__ cursor, int* __restrict__ csrc, int E)
{
    int i = blockIdx.x * blockDim.x + threadIdx.x;
    if (i < E) {
        int p = atomicAdd(&cursor[dst[i]], 1);
        csrc[p] = src[i];
    }
}

// ---------------- per-dst aggregation: edge softmax + weighted gather ----------------
__global__ void __launch_bounds__(256) aggregate_kernel(
    const int* __restrict__ indptr, const int* __restrict__ csrc,
    const float* __restrict__ el, const float* __restrict__ er,
    const float* __restrict__ fs, const float* __restrict__ bias,
    float* __restrict__ out, int n_dst)
{
    int gw = (blockIdx.x * blockDim.x + threadIdx.x) >> 5;
    if (gw >= n_dst) return;
    const int lane = threadIdx.x & 31;
    const int node = gw;
    const int start = indptr[node], end = indptr[node + 1];
    const int h = lane >> 3;

    float4 ern = __ldg(reinterpret_cast<const float4*>(er) + node);
    float er_h = (h == 0) ? ern.x : (h == 1) ? ern.y : (h == 2) ? ern.z : ern.w;

    float4 m4 = make_float4(-INFINITY, -INFINITY, -INFINITY, -INFINITY);
    for (int i = start + lane; i < end; i += 32) {
        int s = csrc[i];
        float4 ev = __ldg(reinterpret_cast<const float4*>(el) + s);
        m4.x = fmaxf(m4.x, lrelu(ev.x + ern.x));
        m4.y = fmaxf(m4.y, lrelu(ev.y + ern.y));
        m4.z = fmaxf(m4.z, lrelu(ev.z + ern.z));
        m4.w = fmaxf(m4.w, lrelu(ev.w + ern.w));
    }
#pragma unroll
    for (int o = 16; o > 0; o >>= 1) {
        m4.x = fmaxf(m4.x, __shfl_xor_sync(0xffffffffu, m4.x, o));
        m4.y = fmaxf(m4.y, __shfl_xor_sync(0xffffffffu, m4.y, o));
        m4.z = fmaxf(m4.z, __shfl_xor_sync(0xffffffffu, m4.z, o));
        m4.w = fmaxf(m4.w, __shfl_xor_sync(0xffffffffu, m4.w, o));
    }
    float m_h = (h == 0) ? m4.x : (h == 1) ? m4.y : (h == 2) ? m4.z : m4.w;

    float sum_w = 0.f;
    float4 acc = make_float4(0.f, 0.f, 0.f, 0.f);
    const float4* fs4 = reinterpret_cast<const float4*>(fs);
    for (int i = start; i < end; i++) {
        int s = csrc[i];
        float elh = __ldg(el + (size_t)s * 4 + h);
        float w = __expf(lrelu(elh + er_h) - m_h);
        sum_w += w;
        float4 f = fs4[(size_t)s * 32 + lane];
        acc.x = fmaf(w, f.x, acc.x);
        acc.y = fmaf(w, f.y, acc.y);
        acc.z = fmaf(w, f.z, acc.z);
        acc.w = fmaf(w, f.w, acc.w);
    }
    float inv = (end > start) ? (1.0f / sum_w) : 0.f;
    float4 b = reinterpret_cast<const float4*>(bias)[lane];
    float4 o;
    o.x = fmaf(acc.x, inv, b.x);
    o.y = fmaf(acc.y, inv, b.y);
    o.z = fmaf(acc.z, inv, b.z);
    o.w = fmaf(acc.w, inv, b.w);
    reinterpret_cast<float4*>(out)[(size_t)node * 32 + lane] = o;
}

// ---------------- launch ----------------
extern "C" void kernel_launch(void* const* d_in, const int* in_sizes, int n_in,
                              void* d_out, int out_size)
{
    const float* x_drug  = (const float*)d_in[0];
    const float* x_prot  = (const float*)d_in[1];
    const int*   src_dp  = (const int*)d_in[2];
    const int*   dst_dp  = (const int*)d_in[3];
    const int*   src_pd  = (const int*)d_in[4];
    const int*   dst_pd  = (const int*)d_in[5];
    const float* W_in_d  = (const float*)d_in[6];
    const float* b_in_d  = (const float*)d_in[7];
    const float* W_in_p  = (const float*)d_in[8];
    const float* b_in_p  = (const float*)d_in[9];
    const float* W_dp    = (const float*)d_in[10];
    const float* al_dp   = (const float*)d_in[11];
    const float* ar_dp   = (const float*)d_in[12];
    const float* bias_dp = (const float*)d_in[13];
    const float* W_pd    = (const float*)d_in[14];
    const float* al_pd   = (const float*)d_in[15];
    const float* ar_pd   = (const float*)d_in[16];
    const float* bias_pd = (const float*)d_in[17];
    const float* W_out_d = (const float*)d_in[18];
    const float* b_out_d = (const float*)d_in[19];
    const float* W_out_p = (const float*)d_in[20];
    const float* b_out_p = (const float*)d_in[21];
    float* out = (float*)d_out;

    const int n_drug = in_sizes[0] / HID;
    const int n_prot = in_sizes[1] / HID;
    const int E = in_sizes[2];

    float *h_d, *h_p, *fs_d, *fs_p, *agg_d, *agg_p, *el_d, *er_p, *el_p, *er_d, *Ut_dp, *Ut_pd;
    int *deg_p, *deg_d, *indptr_p, *indptr_d, *cursor_p, *cursor_d, *csrc_p, *csrc_d, *part_p, *part_d;
    __nv_bfloat16* wimg;
    cudaGetSymbolAddress((void**)&h_d, g_h_d);
    cudaGetSymbolAddress((void**)&h_p, g_h_p);
    cudaGetSymbolAddress((void**)&fs_d, g_fs_d);
    cudaGetSymbolAddress((void**)&fs_p, g_fs_p);
    cudaGetSymbolAddress((void**)&agg_d, g_agg_d);
    cudaGetSymbolAddress((void**)&agg_p, g_agg_p);
    cudaGetSymbolAddress((void**)&el_d, g_el_d);
    cudaGetSymbolAddress((void**)&er_p, g_er_p);
    cudaGetSymbolAddress((void**)&el_p, g_el_p);
    cudaGetSymbolAddress((void**)&er_d, g_er_d);
    cudaGetSymbolAddress((void**)&Ut_dp, g_Ut_dp);
    cudaGetSymbolAddress((void**)&Ut_pd, g_Ut_pd);
    cudaGetSymbolAddress((void**)&deg_p, g_deg_p);
    cudaGetSymbolAddress((void**)&deg_d, g_deg_d);
    cudaGetSymbolAddress((void**)&indptr_p, g_indptr_p);
    cudaGetSymbolAddress((void**)&indptr_d, g_indptr_d);
    cudaGetSymbolAddress((void**)&cursor_p, g_cursor_p);
    cudaGetSymbolAddress((void**)&cursor_d, g_cursor_d);
    cudaGetSymbolAddress((void**)&csrc_p, g_csrc_p);
    cudaGetSymbolAddress((void**)&csrc_d, g_csrc_d);
    cudaGetSymbolAddress((void**)&part_p, g_part_p);
    cudaGetSymbolAddress((void**)&part_d, g_part_d);
    cudaGetSymbolAddress((void**)&wimg, g_wimg);

    __nv_bfloat16* img[6][2];
    for (int m = 0; m < 6; m++)
        for (int s = 0; s < 2; s++)
            img[m][s] = wimg + ((size_t)m * 2 + s) * 128 * 128;

    cudaFuncSetAttribute(gemm_mma<true,  true >, cudaFuncAttributeMaxDynamicSharedMemorySize, SM_TOTAL);
    cudaFuncSetAttribute(gemm_mma<false, false>, cudaFuncAttributeMaxDynamicSharedMemorySize, SM_TOTAL);
    cudaFuncSetAttribute(gemm_mma<false, true >, cudaFuncAttributeMaxDynamicSharedMemorySize, SM_TOTAL);

    const int gd = (n_drug + 127) / 128;
    const int gp = (n_prot + 127) / 128;
    const int ge = (E + 255) / 256;
    const int nb_p = (n_prot + 1023) / 1024;
    const int nb_d = (n_drug + 1023) / 1024;

    // launches 1-5: zero x2, count x2, prep_w(W_in_d)
    zero_kernel<<<(n_prot + 255) / 256, 256>>>(deg_p, n_prot);              // 1
    zero_kernel<<<(n_drug + 255) / 256, 256>>>(deg_d, n_drug);              // 2
    count_kernel<<<ge, 256>>>(dst_dp, deg_p, E);                            // 3
    count_kernel<<<ge, 256>>>(dst_pd, deg_d, E);                            // 4
    prep_w_kernel<<<64, 256>>>(W_in_d, img[0][0], img[0][1]);               // 5
    // launch 6 (ncu -s 5 -c 1 profiles THIS): first tensor GEMM
    gemm_mma<true, true><<<gd, 256, SM_TOTAL>>>(x_drug, img[0][0], img[0][1], b_in_d, h_d, n_drug);  // 6

    // remaining prep
    prep_w_kernel<<<64, 256>>>(W_in_p,  img[1][0], img[1][1]);
    prep_w_kernel<<<64, 256>>>(W_dp,    img[2][0], img[2][1]);
    prep_w_kernel<<<64, 256>>>(W_pd,    img[3][0], img[3][1]);
    prep_w_kernel<<<64, 256>>>(W_out_d, img[4][0], img[4][1]);
    prep_w_kernel<<<64, 256>>>(W_out_p, img[5][0], img[5][1]);
    fold_attn_kernel<<<1, 128>>>(W_dp, ar_dp, Ut_dp);
    fold_attn_kernel<<<1, 128>>>(W_pd, ar_pd, Ut_pd);

    // CSR build (counts already done)
    scan_partA<<<nb_p, 1024>>>(deg_p, part_p, n_prot);
    scan_partA<<<nb_d, 1024>>>(deg_d, part_d, n_drug);
    scan_partB<<<1, 1024>>>(part_p, indptr_p, nb_p, n_prot);
    scan_partB<<<1, 1024>>>(part_d, indptr_d, nb_d, n_drug);
    scan_partC<<<nb_p, 1024>>>(deg_p, part_p, indptr_p, cursor_p, n_prot);
    scan_partC<<<nb_d, 1024>>>(deg_d, part_d, indptr_d, cursor_d, n_drug);
    scatter_kernel<<<ge, 256>>>(src_dp, dst_dp, cursor_p, csrc_p, E);
    scatter_kernel<<<ge, 256>>>(src_pd, dst_pd, cursor_d, csrc_d, E);

    // second input projection
    gemm_mma<true, true><<<gp, 256, SM_TOTAL>>>(x_prot, img[1][0], img[1][1], b_in_p, h_p, n_prot);

    // GAT projections: fs; el from fs; er via folded U
    gemm_mma<false, false><<<gd, 256, SM_TOTAL>>>(h_d, img[2][0], img[2][1], nullptr, fs_d, n_drug);
    gemm_mma<false, false><<<gp, 256, SM_TOTAL>>>(h_p, img[3][0], img[3][1], nullptr, fs_p, n_prot);
    el_kernel<<<(n_drug * 32 + 255) / 256, 256>>>(fs_d, al_dp, el_d, n_drug);
    el_kernel<<<(n_prot * 32 + 255) / 256, 256>>>(fs_p, al_pd, el_p, n_prot);
    er_kernel<<<(n_prot * 32 + 255) / 256, 256>>>(h_p, Ut_dp, er_p, n_prot);
    er_kernel<<<(n_drug * 32 + 255) / 256, 256>>>(h_d, Ut_pd, er_d, n_drug);

    // edge softmax + aggregation
    aggregate_kernel<<<(n_prot * 32 + 255) / 256, 256>>>(indptr_p, csrc_p, el_d, er_p, fs_d, bias_dp, agg_p, n_prot);
    aggregate_kernel<<<(n_drug * 32 + 255) / 256, 256>>>(indptr_d, csrc_d, el_p, er_d, fs_p, bias_pd, agg_d, n_drug);

    // output projections -> d_out
    gemm_mma<false, true><<<gd, 256, SM_TOTAL>>>(agg_d, img[4][0], img[4][1], b_out_d, out, n_drug);
    gemm_mma<false, true><<<gp, 256, SM_TOTAL>>>(agg_p, img[5][0], img[5][1], b_out_p, out + (size_t)n_drug * HID, n_prot);
}

// round 8
// speedup vs baseline: 1.2833x; 1.2833x over previous
#include <cuda_runtime.h>
#include <math.h>
#include <stdint.h>

// ---------------- problem constants ----------------
#define ND 100000
#define NP 100000
#define EE 800000
#define HID 128

// ---------------- scratch (device globals) ----------------
__device__ float g_h_d[ND * HID];
__device__ float g_h_p[NP * HID];
__device__ float g_fs_d[ND * HID];
__device__ float g_fs_p[NP * HID];
__device__ float g_agg_d[ND * HID];
__device__ float g_agg_p[NP * HID];
__device__ float g_el_d[ND * 4];
__device__ float g_er_p[NP * 4];
__device__ float g_el_p[NP * 4];
__device__ float g_er_d[ND * 4];
__device__ float g_Ut_dp[4 * HID];
__device__ float g_Ut_pd[4 * HID];
__device__ int g_deg_p[NP];
__device__ int g_deg_d[ND];
__device__ int g_indptr_p[NP + 1];
__device__ int g_indptr_d[ND + 1];
__device__ int g_cursor_p[NP + 1];
__device__ int g_cursor_d[ND + 1];
__device__ int g_csrc_p[EE];
__device__ int g_csrc_d[EE];
__device__ int g_part_p[1024];
__device__ int g_part_d[1024];

__device__ __forceinline__ float lrelu(float v) { return v > 0.f ? v : 0.2f * v; }

// ---------------- packed f32x2 helpers (Blackwell FFMA2) ----------------
__device__ __forceinline__ unsigned long long pk2(float x, float y) {
    unsigned long long r;
    asm("mov.b64 %0, {%1, %2};" : "=l"(r) : "f"(x), "f"(y));
    return r;
}
__device__ __forceinline__ void fma2(unsigned long long& d, unsigned long long a,
                                     unsigned long long b) {
    asm("fma.rn.f32x2 %0, %1, %2, %0;" : "+l"(d) : "l"(a), "l"(b));
}
__device__ __forceinline__ void upk2(float& x, float& y, unsigned long long v) {
    asm("mov.b64 {%0, %1}, %2;" : "=f"(x), "=f"(y) : "l"(v));
}

// ---------------- GEMM: [M,128] x [128,128], packed f32x2 FMA ----------------
// Block = 256 threads; 64-row panel; warp -> 8 rows; lane -> 4 consecutive cols.
template <bool RELU, bool HAS_BIAS, bool ATTN>
__global__ void __launch_bounds__(256, 2) gemm_f2(
    const float* __restrict__ A, const float* __restrict__ W,
    const float* __restrict__ bias, float* __restrict__ out,
    const float* __restrict__ attn, float* __restrict__ evec, int M)
{
    extern __shared__ float smem[];
    float* sW = smem;            // 128*128 floats (64KB)
    float* sA = smem + 16384;    // 64*128 floats (32KB)
    const int tid = threadIdx.x;

    float4* sW4 = reinterpret_cast<float4*>(sW);
    const float4* W4 = reinterpret_cast<const float4*>(W);
#pragma unroll
    for (int i = 0; i < 16; i++) sW4[tid + 256 * i] = W4[tid + 256 * i];

    const int row0 = blockIdx.x * 64;
    float4* sA4 = reinterpret_cast<float4*>(sA);
    const float4* A4 = reinterpret_cast<const float4*>(A);
    int nrows = M - row0;
    if (nrows > 64) nrows = 64;
    for (int i = tid; i < nrows * 32; i += 256) sA4[i] = A4[(size_t)row0 * 32 + i];
    for (int i = nrows * 32 + tid; i < 64 * 32; i += 256)
        sA4[i] = make_float4(0.f, 0.f, 0.f, 0.f);
    __syncthreads();

    const int warp = tid >> 5, lane = tid & 31;
    const int rbase = warp * 8;

    unsigned long long acc01[8], acc23[8];
#pragma unroll
    for (int r = 0; r < 8; r++) { acc01[r] = 0ull; acc23[r] = 0ull; }

#pragma unroll 4
    for (int k = 0; k < 128; k += 2) {
        float4 wv0 = sW4[k * 32 + lane];
        float4 wv1 = sW4[(k + 1) * 32 + lane];
        unsigned long long w0a = pk2(wv0.x, wv0.y), w0b = pk2(wv0.z, wv0.w);
        unsigned long long w1a = pk2(wv1.x, wv1.y), w1b = pk2(wv1.z, wv1.w);
#pragma unroll
        for (int r = 0; r < 8; r++) {
            float2 a2 = *reinterpret_cast<const float2*>(&sA[(rbase + r) * 128 + k]);
            unsigned long long aa0 = pk2(a2.x, a2.x);
            unsigned long long aa1 = pk2(a2.y, a2.y);
            fma2(acc01[r], aa0, w0a);
            fma2(acc23[r], aa0, w0b);
            fma2(acc01[r], aa1, w1a);
            fma2(acc23[r], aa1, w1b);
        }
    }

    float4 bv = make_float4(0.f, 0.f, 0.f, 0.f);
    if (HAS_BIAS) bv = reinterpret_cast<const float4*>(bias)[lane];
    float4 av = make_float4(0.f, 0.f, 0.f, 0.f);
    if (ATTN) av = reinterpret_cast<const float4*>(attn)[lane];

#pragma unroll
    for (int r = 0; r < 8; r++) {
        int row = row0 + rbase + r;
        if (row >= M) break;
        float c0, c1, c2, c3;
        upk2(c0, c1, acc01[r]);
        upk2(c2, c3, acc23[r]);
        if (ATTN) {
            // per-head dot: cols [lane*4..lane*4+3] all lie in head lane>>3
            float p = c0 * av.x + c1 * av.y + c2 * av.z + c3 * av.w;
            p += __shfl_xor_sync(0xffffffffu, p, 1);
            p += __shfl_xor_sync(0xffffffffu, p, 2);
            p += __shfl_xor_sync(0xffffffffu, p, 4);
            if ((lane & 7) == 0) evec[(size_t)row * 4 + (lane >> 3)] = p;
        }
        float4 o;
        o.x = c0 + bv.x; o.y = c1 + bv.y; o.z = c2 + bv.z; o.w = c3 + bv.w;
        if (RELU) {
            o.x = fmaxf(o.x, 0.f); o.y = fmaxf(o.y, 0.f);
            o.z = fmaxf(o.z, 0.f); o.w = fmaxf(o.w, 0.f);
        }
        reinterpret_cast<float4*>(out)[(size_t)row * 32 + lane] = o;
    }
}

// ---------------- misc small kernels ----------------
__global__ void zero_kernel(int* __restrict__ a, int n)
{
    int i = blockIdx.x * blockDim.x + threadIdx.x;
    if (i < n) a[i] = 0;
}

__global__ void fold_attn_kernel(const float* __restrict__ W,
                                 const float* __restrict__ ar,
                                 float* __restrict__ Ut)
{
    int k = threadIdx.x;
#pragma unroll
    for (int h = 0; h < 4; h++) {
        float s = 0.f;
#pragma unroll
        for (int d = 0; d < 32; d++)
            s += W[k * 128 + h * 32 + d] * ar[h * 32 + d];
        Ut[h * 128 + k] = s;
    }
}

__global__ void __launch_bounds__(256) er_kernel(
    const float* __restrict__ hfeat, const float* __restrict__ Ut,
    float* __restrict__ er, int n)
{
    int gw = (blockIdx.x * blockDim.x + threadIdx.x) >> 5;
    if (gw >= n) return;
    const int lane = threadIdx.x & 31;
    float4 f = reinterpret_cast<const float4*>(hfeat)[(size_t)gw * 32 + lane];
    const float4* Ut4 = reinterpret_cast<const float4*>(Ut);
    float p[4];
#pragma unroll
    for (int h = 0; h < 4; h++) {
        float4 u = __ldg(Ut4 + h * 32 + lane);
        p[h] = f.x * u.x + f.y * u.y + f.z * u.z + f.w * u.w;
    }
#pragma unroll
    for (int o = 16; o > 0; o >>= 1) {
#pragma unroll
        for (int h = 0; h < 4; h++)
            p[h] += __shfl_xor_sync(0xffffffffu, p[h], o);
    }
    if (lane == 0)
        reinterpret_cast<float4*>(er)[gw] = make_float4(p[0], p[1], p[2], p[3]);
}

// ---------------- CSR build ----------------
__global__ void count_kernel(const int* __restrict__ dst, int* __restrict__ deg, int E)
{
    int i = blockIdx.x * blockDim.x + threadIdx.x;
    if (i < E) atomicAdd(&deg[dst[i]], 1);
}

__global__ void __launch_bounds__(1024) scan_partA(const int* __restrict__ deg,
                                                   int* __restrict__ part, int n)
{
    __shared__ int ws[32];
    const int tid = threadIdx.x, lane = tid & 31, wid = tid >> 5;
    int i = blockIdx.x * 1024 + tid;
    int v = (i < n) ? deg[i] : 0;
    int s = v;
#pragma unroll
    for (int o = 16; o > 0; o >>= 1) s += __shfl_xor_sync(0xffffffffu, s, o);
    if (lane == 0) ws[wid] = s;
    __syncthreads();
    if (wid == 0) {
        int t = ws[lane];
#pragma unroll
        for (int o = 16; o > 0; o >>= 1) t += __shfl_xor_sync(0xffffffffu, t, o);
        if (lane == 0) part[blockIdx.x] = t;
    }
}

__global__ void __launch_bounds__(1024) scan_partB(int* __restrict__ part,
                                                   int* __restrict__ indptr,
                                                   int nb, int n)
{
    __shared__ int ws[32];
    const int tid = threadIdx.x, lane = tid & 31, wid = tid >> 5;
    int v = (tid < nb) ? part[tid] : 0;
    int x = v;
#pragma unroll
    for (int o = 1; o < 32; o <<= 1) {
        int y = __shfl_up_sync(0xffffffffu, x, o);
        if (lane >= o) x += y;
    }
    if (lane == 31) ws[wid] = x;
    __syncthreads();
    if (wid == 0) {
        int s = ws[lane];
#pragma unroll
        for (int o = 1; o < 32; o <<= 1) {
            int y = __shfl_up_sync(0xffffffffu, s, o);
            if (lane >= o) s += y;
        }
        ws[lane] = s;
    }
    __syncthreads();
    int excl = x - v + (wid ? ws[wid - 1] : 0);
    if (tid < nb) part[tid] = excl;
    __syncthreads();
    if (tid == 0) indptr[n] = ws[31];
}

__global__ void __launch_bounds__(1024) scan_partC(const int* __restrict__ deg,
                                                   const int* __restrict__ part,
                                                   int* __restrict__ indptr,
                                                   int* __restrict__ cursor, int n)
{
    __shared__ int ws[32];
    const int tid = threadIdx.x, lane = tid & 31, wid = tid >> 5;
    int i = blockIdx.x * 1024 + tid;
    int v = (i < n) ? deg[i] : 0;
    int x = v;
#pragma unroll
    for (int o = 1; o < 32; o <<= 1) {
        int y = __shfl_up_sync(0xffffffffu, x, o);
        if (lane >= o) x += y;
    }
    if (lane == 31) ws[wid] = x;
    __syncthreads();
    if (wid == 0) {
        int s = ws[lane];
#pragma unroll
        for (int o = 1; o < 32; o <<= 1) {
            int y = __shfl_up_sync(0xffffffffu, s, o);
            if (lane >= o) s += y;
        }
        ws[lane] = s;
    }
    __syncthreads();
    int excl = part[blockIdx.x] + x - v + (wid ? ws[wid - 1] : 0);
    if (i < n) { indptr[i] = excl; cursor[i] = excl; }
}

__global__ void scatter_kernel(const int* __restrict__ src, const int* __restrict__ dst,
                               int* __restrict__ cursor, int* __restrict__ csrc, int E)
{
    int i = blockIdx.x * blockDim.x + threadIdx.x;
    if (i < E) {
        int p = atomicAdd(&cursor[dst[i]], 1);
        csrc[p] = src[i];
    }
}

// ---------------- per-dst aggregation: edge softmax + weighted gather ----------------
__global__ void __launch_bounds__(256) aggregate_kernel(
    const int* __restrict__ indptr, const int* __restrict__ csrc,
    const float* __restrict__ el, const float* __restrict__ er,
    const float* __restrict__ fs, const float* __restrict__ bias,
    float* __restrict__ out, int n_dst)
{
    int gw = (blockIdx.x * blockDim.x + threadIdx.x) >> 5;
    if (gw >= n_dst) return;
    const int lane = threadIdx.x & 31;
    const int node = gw;
    const int start = indptr[node], end = indptr[node + 1];
    const int h = lane >> 3;

    float4 ern = __ldg(reinterpret_cast<const float4*>(er) + node);
    float er_h = (h == 0) ? ern.x : (h == 1) ? ern.y : (h == 2) ? ern.z : ern.w;

    float4 m4 = make_float4(-INFINITY, -INFINITY, -INFINITY, -INFINITY);
    for (int i = start + lane; i < end; i += 32) {
        int s = csrc[i];
        float4 ev = __ldg(reinterpret_cast<const float4*>(el) + s);
        m4.x = fmaxf(m4.x, lrelu(ev.x + ern.x));
        m4.y = fmaxf(m4.y, lrelu(ev.y + ern.y));
        m4.z = fmaxf(m4.z, lrelu(ev.z + ern.z));
        m4.w = fmaxf(m4.w, lrelu(ev.w + ern.w));
    }
#pragma unroll
    for (int o = 16; o > 0; o >>= 1) {
        m4.x = fmaxf(m4.x, __shfl_xor_sync(0xffffffffu, m4.x, o));
        m4.y = fmaxf(m4.y, __shfl_xor_sync(0xffffffffu, m4.y, o));
        m4.z = fmaxf(m4.z, __shfl_xor_sync(0xffffffffu, m4.z, o));
        m4.w = fmaxf(m4.w, __shfl_xor_sync(0xffffffffu, m4.w, o));
    }
    float m_h = (h == 0) ? m4.x : (h == 1) ? m4.y : (h == 2) ? m4.z : m4.w;

    float sum_w = 0.f;
    float4 acc = make_float4(0.f, 0.f, 0.f, 0.f);
    const float4* fs4 = reinterpret_cast<const float4*>(fs);
    for (int i = start; i < end; i++) {
        int s = csrc[i];
        float elh = __ldg(el + (size_t)s * 4 + h);
        float w = __expf(lrelu(elh + er_h) - m_h);
        sum_w += w;
        float4 f = fs4[(size_t)s * 32 + lane];
        acc.x = fmaf(w, f.x, acc.x);
        acc.y = fmaf(w, f.y, acc.y);
        acc.z = fmaf(w, f.z, acc.z);
        acc.w = fmaf(w, f.w, acc.w);
    }
    float inv = (end > start) ? (1.0f / sum_w) : 0.f;
    float4 b = reinterpret_cast<const float4*>(bias)[lane];
    float4 o;
    o.x = fmaf(acc.x, inv, b.x);
    o.y = fmaf(acc.y, inv, b.y);
    o.z = fmaf(acc.z, inv, b.z);
    o.w = fmaf(acc.w, inv, b.w);
    reinterpret_cast<float4*>(out)[(size_t)node * 32 + lane] = o;
}

// ---------------- launch ----------------
extern "C" void kernel_launch(void* const* d_in, const int* in_sizes, int n_in,
                              void* d_out, int out_size)
{
    const float* x_drug  = (const float*)d_in[0];
    const float* x_prot  = (const float*)d_in[1];
    const int*   src_dp  = (const int*)d_in[2];
    const int*   dst_dp  = (const int*)d_in[3];
    const int*   src_pd  = (const int*)d_in[4];
    const int*   dst_pd  = (const int*)d_in[5];
    const float* W_in_d  = (const float*)d_in[6];
    const float* b_in_d  = (const float*)d_in[7];
    const float* W_in_p  = (const float*)d_in[8];
    const float* b_in_p  = (const float*)d_in[9];
    const float* W_dp    = (const float*)d_in[10];
    const float* al_dp   = (const float*)d_in[11];
    const float* ar_dp   = (const float*)d_in[12];
    const float* bias_dp = (const float*)d_in[13];
    const float* W_pd    = (const float*)d_in[14];
    const float* al_pd   = (const float*)d_in[15];
    const float* ar_pd   = (const float*)d_in[16];
    const float* bias_pd = (const float*)d_in[17];
    const float* W_out_d = (const float*)d_in[18];
    const float* b_out_d = (const float*)d_in[19];
    const float* W_out_p = (const float*)d_in[20];
    const float* b_out_p = (const float*)d_in[21];
    float* out = (float*)d_out;

    const int n_drug = in_sizes[0] / HID;
    const int n_prot = in_sizes[1] / HID;
    const int E = in_sizes[2];

    float *h_d, *h_p, *fs_d, *fs_p, *agg_d, *agg_p, *el_d, *er_p, *el_p, *er_d, *Ut_dp, *Ut_pd;
    int *deg_p, *deg_d, *indptr_p, *indptr_d, *cursor_p, *cursor_d, *csrc_p, *csrc_d, *part_p, *part_d;
    cudaGetSymbolAddress((void**)&h_d, g_h_d);
    cudaGetSymbolAddress((void**)&h_p, g_h_p);
    cudaGetSymbolAddress((void**)&fs_d, g_fs_d);
    cudaGetSymbolAddress((void**)&fs_p, g_fs_p);
    cudaGetSymbolAddress((void**)&agg_d, g_agg_d);
    cudaGetSymbolAddress((void**)&agg_p, g_agg_p);
    cudaGetSymbolAddress((void**)&el_d, g_el_d);
    cudaGetSymbolAddress((void**)&er_p, g_er_p);
    cudaGetSymbolAddress((void**)&el_p, g_el_p);
    cudaGetSymbolAddress((void**)&er_d, g_er_d);
    cudaGetSymbolAddress((void**)&Ut_dp, g_Ut_dp);
    cudaGetSymbolAddress((void**)&Ut_pd, g_Ut_pd);
    cudaGetSymbolAddress((void**)&deg_p, g_deg_p);
    cudaGetSymbolAddress((void**)&deg_d, g_deg_d);
    cudaGetSymbolAddress((void**)&indptr_p, g_indptr_p);
    cudaGetSymbolAddress((void**)&indptr_d, g_indptr_d);
    cudaGetSymbolAddress((void**)&cursor_p, g_cursor_p);
    cudaGetSymbolAddress((void**)&cursor_d, g_cursor_d);
    cudaGetSymbolAddress((void**)&csrc_p, g_csrc_p);
    cudaGetSymbolAddress((void**)&csrc_d, g_csrc_d);
    cudaGetSymbolAddress((void**)&part_p, g_part_p);
    cudaGetSymbolAddress((void**)&part_d, g_part_d);

    const int SMEM = (16384 + 8192) * (int)sizeof(float);  // 96 KB
    cudaFuncSetAttribute(gemm_f2<true,  true,  false>, cudaFuncAttributeMaxDynamicSharedMemorySize, SMEM);
    cudaFuncSetAttribute(gemm_f2<false, false, true >, cudaFuncAttributeMaxDynamicSharedMemorySize, SMEM);
    cudaFuncSetAttribute(gemm_f2<false, true,  false>, cudaFuncAttributeMaxDynamicSharedMemorySize, SMEM);

    const int gd = (n_drug + 63) / 64;
    const int gp = (n_prot + 63) / 64;
    const int ge = (E + 255) / 256;
    const int nb_p = (n_prot + 1023) / 1024;
    const int nb_d = (n_drug + 1023) / 1024;

    // CSR build
    zero_kernel<<<(n_prot + 255) / 256, 256>>>(deg_p, n_prot);
    zero_kernel<<<(n_drug + 255) / 256, 256>>>(deg_d, n_drug);
    count_kernel<<<ge, 256>>>(dst_dp, deg_p, E);
    count_kernel<<<ge, 256>>>(dst_pd, deg_d, E);
    scan_partA<<<nb_p, 1024>>>(deg_p, part_p, n_prot);
    scan_partA<<<nb_d, 1024>>>(deg_d, part_d, n_drug);
    scan_partB<<<1, 1024>>>(part_p, indptr_p, nb_p, n_prot);
    scan_partB<<<1, 1024>>>(part_d, indptr_d, nb_d, n_drug);
    scan_partC<<<nb_p, 1024>>>(deg_p, part_p, indptr_p, cursor_p, n_prot);
    scan_partC<<<nb_d, 1024>>>(deg_d, part_d, indptr_d, cursor_d, n_drug);
    scatter_kernel<<<ge, 256>>>(src_dp, dst_dp, cursor_p, csrc_p, E);
    scatter_kernel<<<ge, 256>>>(src_pd, dst_pd, cursor_d, csrc_d, E);

    // fold attn-right vectors into W (tiny)
    fold_attn_kernel<<<1, 128>>>(W_dp, ar_dp, Ut_dp);
    fold_attn_kernel<<<1, 128>>>(W_pd, ar_pd, Ut_pd);

    // input projections (+relu), packed f32x2
    gemm_f2<true, true, false><<<gd, 256, SMEM>>>(x_drug, W_in_d, b_in_d, h_d, nullptr, nullptr, n_drug);
    gemm_f2<true, true, false><<<gp, 256, SMEM>>>(x_prot, W_in_p, b_in_p, h_p, nullptr, nullptr, n_prot);

    // GAT projections: fs (+el fused); er via folded U
    gemm_f2<false, false, true><<<gd, 256, SMEM>>>(h_d, W_dp, nullptr, fs_d, al_dp, el_d, n_drug);
    gemm_f2<false, false, true><<<gp, 256, SMEM>>>(h_p, W_pd, nullptr, fs_p, al_pd, el_p, n_prot);
    er_kernel<<<(n_prot * 32 + 255) / 256, 256>>>(h_p, Ut_dp, er_p, n_prot);
    er_kernel<<<(n_drug * 32 + 255) / 256, 256>>>(h_d, Ut_pd, er_d, n_drug);

    // edge softmax + aggregation
    aggregate_kernel<<<(n_prot * 32 + 255) / 256, 256>>>(indptr_p, csrc_p, el_d, er_p, fs_d, bias_dp, agg_p, n_prot);
    aggregate_kernel<<<(n_drug * 32 + 255) / 256, 256>>>(indptr_d, csrc_d, el_p, er_d, fs_p, bias_pd, agg_d, n_drug);

    // output projections -> d_out
    gemm_f2<false, true, false><<<gd, 256, SMEM>>>(agg_d, W_out_d, b_out_d, out, nullptr, nullptr, n_drug);
    gemm_f2<false, true, false><<<gp, 256, SMEM>>>(agg_p, W_out_p, b_out_p, out + (size_t)n_drug * HID, nullptr, nullptr, n_prot);
}